// round 17
// baseline (speedup 1.0000x reference)
#include <cuda_runtime.h>
#include <cuda_fp16.h>
#include <cuda_bf16.h>
#include <math.h>
#include <stdint.h>

// Shapes fixed by the dataset: B=64, F=512, S=8192, E=500000, D=1024.
#define BB    64
#define FF    512
#define S_MAX 8192
#define D_MAX 1024
#define NSIM  256            // sim tiles: 8192 / 32
#define NSCAT 128            // edge-scatter blocks
#define EPSV  1e-8f
#define ETA   0.01f

// ---------------- device scratch (static: no allocations allowed) ------------
__device__ __align__(16) __nv_bfloat16 g_HnB[BB * FF]; // normalized heatmap bf16 [b][f]
__device__ float  g_gnorm[BB];                          // ||grad_b||
__device__ __align__(16) __half g_simN[BB * S_MAX];     // sim [b][s], fp16 (s contiguous)
__device__ __align__(16) __half g_W[D_MAX * S_MAX];     // dense edge-weight matrix [d][s]
__device__ __align__(16) float  g_C[D_MAX * BB];        // fp32 GEMM partials [d][b]
__device__ int    g_tick2 = 0;                          // GEMM completion ticket

// ================= portable tensor-core helpers (sm_80+) =====================
__device__ __forceinline__ uint32_t smem_u32(const void* p) {
    uint32_t a;
    asm("{ .reg .u64 t; cvta.to.shared.u64 t, %1; cvt.u32.u64 %0, t; }"
        : "=r"(a) : "l"(p));
    return a;
}
#define LDSM_X4(r, addr)                                                       \
    asm volatile("ldmatrix.sync.aligned.m8n8.x4.shared.b16 {%0,%1,%2,%3}, [%4];" \
        : "=r"((r)[0]), "=r"((r)[1]), "=r"((r)[2]), "=r"((r)[3])               \
        : "r"(addr))
#define LDSM_X2(r0, r1, addr)                                                  \
    asm volatile("ldmatrix.sync.aligned.m8n8.x2.shared.b16 {%0,%1}, [%2];"     \
        : "=r"(r0), "=r"(r1) : "r"(addr))
__device__ __forceinline__ void mma_bf16(float* c, const uint32_t* a,
                                         uint32_t b0, uint32_t b1) {
    asm volatile(
        "mma.sync.aligned.m16n8k16.row.col.f32.bf16.bf16.f32 "
        "{%0,%1,%2,%3}, {%4,%5,%6,%7}, {%8,%9}, {%0,%1,%2,%3};"
        : "+f"(c[0]), "+f"(c[1]), "+f"(c[2]), "+f"(c[3])
        : "r"(a[0]), "r"(a[1]), "r"(a[2]), "r"(a[3]), "r"(b0), "r"(b1));
}
__device__ __forceinline__ void mma_f16(float* c, const uint32_t* a,
                                        uint32_t b0, uint32_t b1) {
    asm volatile(
        "mma.sync.aligned.m16n8k16.row.col.f32.f16.f16.f32 "
        "{%0,%1,%2,%3}, {%4,%5,%6,%7}, {%8,%9}, {%0,%1,%2,%3};"
        : "+f"(c[0]), "+f"(c[1]), "+f"(c[2]), "+f"(c[3])
        : "r"(a[0]), "r"(a[1]), "r"(a[2]), "r"(a[3]), "r"(b0), "r"(b1));
}

// ---------------- K1: prep_h (blocks 0..15) + zero W,C (blocks 16..145) -----
// Zero space: W = 1048576 uint4, C = 16384 uint4; 130 blocks x 8192 = exact.
__global__ void __launch_bounds__(512, 1)
combo_kernel(const float* __restrict__ H, const float* __restrict__ G) {
    int t = threadIdx.x;                   // 512
    if (blockIdx.x < 16) {
        __shared__ float wsh[4][4], wsg[4][4], sinvs[4];
        int r  = t >> 7;                   // row group 0..3
        int tt = t & 127;
        int b  = blockIdx.x * 4 + r;       // 0..63
        float4 hv = reinterpret_cast<const float4*>(H + b * FF)[tt];
        float4 gv = reinterpret_cast<const float4*>(G + b * FF)[tt];
        float sh = hv.x * hv.x + hv.y * hv.y + hv.z * hv.z + hv.w * hv.w;
        float sg = gv.x * gv.x + gv.y * gv.y + gv.z * gv.z + gv.w * gv.w;
        #pragma unroll
        for (int o = 16; o > 0; o >>= 1) {
            sh += __shfl_down_sync(0xffffffffu, sh, o);
            sg += __shfl_down_sync(0xffffffffu, sg, o);
        }
        if ((tt & 31) == 0) { wsh[r][tt >> 5] = sh; wsg[r][tt >> 5] = sg; }
        __syncthreads();
        if (tt == 0) {
            float th = wsh[r][0] + wsh[r][1] + wsh[r][2] + wsh[r][3];
            float tg = wsg[r][0] + wsg[r][1] + wsg[r][2] + wsg[r][3];
            sinvs[r] = 1.0f / (sqrtf(th) + EPSV);
            g_gnorm[b] = sqrtf(tg);
        }
        __syncthreads();
        float inv = sinvs[r];
        __nv_bfloat162 p0 = __floats2bfloat162_rn(hv.x * inv, hv.y * inv);
        __nv_bfloat162 p1 = __floats2bfloat162_rn(hv.z * inv, hv.w * inv);
        uint2 u;
        u.x = *reinterpret_cast<uint32_t*>(&p0);
        u.y = *reinterpret_cast<uint32_t*>(&p1);
        reinterpret_cast<uint2*>(g_HnB)[b * 128 + tt] = u;
    } else {
        int zb = blockIdx.x - 16;          // 0..129
        uint4 z = make_uint4(0, 0, 0, 0);
        uint4* Wu = reinterpret_cast<uint4*>(g_W);
        uint4* Cu = reinterpret_cast<uint4*>(g_C);
        #pragma unroll
        for (int i = 0; i < 16; i++) {
            int idx = zb * 8192 + i * 512 + t;
            if (idx < 1048576) Wu[idx] = z;
            else               Cu[idx - 1048576] = z;
        }
    }
}

// ---------------- K2: FUSED sim (blocks 0..255) + W-scatter (256..383) -------
// sim tile: M=32 signs x N=64 batch x K=512; 512 thr, 16 warps, warp 16x8.
// Writes simN[b][s] fp16. Scatter: per edge, f16x2 RED into dense W[d][s].
#define APITCH    1040                      // bytes per 512-bf16 row (+16 pad)
#define FS_A_OFF  0
#define FS_B_OFF  (32 * APITCH)
#define FS_SMEM   (96 * APITCH)             // 99840 B

__global__ void __launch_bounds__(512, 2)
fused_kernel(const float* __restrict__ SF,
             const float* __restrict__ ew,
             const int* __restrict__ ed,
             const int* __restrict__ es, int E, int CH) {
    extern __shared__ char sm[];
    int t   = threadIdx.x;         // 512
    int bid = blockIdx.x;

    if (bid >= NSIM) {
        // ================== W-scatter branch ==================
        int scid = bid - NSIM;     // 0..NSCAT-1
        int e0 = scid * CH;
        int e1 = min(E, e0 + CH);
        for (int e = e0 + t; e < e1; e += 512) {
            int d = ed[e];
            int s = es[e];
            __half hw = __float2half_rn(ew[e]);
            __half z  = __ushort_as_half(0);
            __half2 v = (s & 1) ? __halves2half2(z, hw) : __halves2half2(hw, z);
            atomicAdd(reinterpret_cast<__half2*>(g_W + (size_t)d * S_MAX + (s & ~1)), v);
        }
        return;
    }

    // ================== sim branch ==================
    int sid = bid;                 // 0..NSIM-1
    int s0  = sid * 32;
    int wid = t >> 5;              // 0..15
    int lid = t & 31;
    __shared__ float s_sinv[32];
    uint32_t smA = smem_u32(sm) + FS_A_OFF;
    uint32_t smB = smem_u32(sm) + FS_B_OFF;

    // Stage A: S tile [32 rows][512 f] fp32 -> bf16, pitch 1040 (MLP 8).
    {
        int q  = t & 127;
        int rr = t >> 7;           // 0..3
        #pragma unroll 8
        for (int j = 0; j < 8; j++) {
            int row = rr + 4 * j;
            float4 v = reinterpret_cast<const float4*>(SF)[(size_t)(s0 + row) * 128 + q];
            __nv_bfloat162 b0 = __floats2bfloat162_rn(v.x, v.y);
            __nv_bfloat162 b1 = __floats2bfloat162_rn(v.z, v.w);
            uint2 u;
            u.x = *reinterpret_cast<uint32_t*>(&b0);
            u.y = *reinterpret_cast<uint32_t*>(&b1);
            *reinterpret_cast<uint2*>(sm + FS_A_OFF + row * APITCH + q * 8) = u;
        }
    }
    // Stage B: Hn [64 rows][512 f] bf16 -> pitch 1040 (L2-hot).
    #pragma unroll 8
    for (int i = t; i < 64 * 64; i += 512) {
        int row = i >> 6;
        int c16 = i & 63;
        uint4 u = reinterpret_cast<const uint4*>(g_HnB)[row * 64 + c16];
        *reinterpret_cast<uint4*>(sm + FS_B_OFF + row * APITCH + c16 * 16) = u;
    }
    __syncthreads();

    // Per-row sumsq from staged bf16 (warp w -> rows 2w, 2w+1).
    #pragma unroll
    for (int rr = 0; rr < 2; rr++) {
        int row = wid * 2 + rr;
        const uint32_t* rp = reinterpret_cast<const uint32_t*>(sm + FS_A_OFF + row * APITCH);
        float sq = 0.f;
        #pragma unroll
        for (int j = 0; j < 8; j++) {
            uint32_t pk = rp[lid + 32 * j];
            __nv_bfloat162 bb = *reinterpret_cast<__nv_bfloat162*>(&pk);
            float2 f = __bfloat1622float2(bb);
            sq += f.x * f.x + f.y * f.y;
        }
        #pragma unroll
        for (int o = 16; o > 0; o >>= 1) sq += __shfl_down_sync(0xffffffffu, sq, o);
        if (lid == 0) s_sinv[row] = 0.5f / (sqrtf(sq) + EPSV);
    }
    __syncthreads();

    // Warp tile: m0 = 16*(wid>>3), n0 = 8*(wid&7). One m16n8k16 per k-step.
    int m0 = (wid >> 3) * 16;
    int n0 = (wid & 7) * 8;
    float c[4] = {0.f, 0.f, 0.f, 0.f};

    uint32_t aBase = smA + (uint32_t)(m0 + (lid & 15)) * APITCH + ((lid >> 4) << 4);
    uint32_t bBase = smB + (uint32_t)(n0 + (lid & 7)) * APITCH + (((lid >> 3) & 1) << 4);

    #pragma unroll 8
    for (int k = 0; k < FF; k += 16) {
        uint32_t a[4], b0v, b1v;
        LDSM_X4(a, aBase + k * 2);
        LDSM_X2(b0v, b1v, bBase + k * 2);
        mma_bf16(c, a, b0v, b1v);
    }

    // Epilogue -> simN[b][s] (2B scattered stores; 8-lane runs merge to 16B).
    int r0 = m0 + (lid >> 2);
    int r1 = r0 + 8;
    int col = n0 + 2 * (lid & 3);
    float sc0 = s_sinv[r0];
    float sc1 = s_sinv[r1];
    g_simN[(size_t)col       * S_MAX + s0 + r0] = __float2half_rn(c[0] * sc0 + 0.5f);
    g_simN[(size_t)(col + 1) * S_MAX + s0 + r0] = __float2half_rn(c[1] * sc0 + 0.5f);
    g_simN[(size_t)col       * S_MAX + s0 + r1] = __float2half_rn(c[2] * sc1 + 0.5f);
    g_simN[(size_t)(col + 1) * S_MAX + s0 + r1] = __float2half_rn(c[3] * sc1 + 0.5f);
}

// ---------------- K3: out GEMM: C[d][b] = sum_s W[d][s]*simN[b][s] -----------
// Grid 128 = 16 m-tiles (64 d) x 8 k-splits (1024 s). 512 thr = 16 warps =
// 4 m-strips x 4 k-quarters. Per chunk (k64): stage simN [n64][k64] in smem
// (shared by the 4 m-strips), A-frags direct from W. fp32 RED partials into
// g_C; decoupled last block applies ETA*gnorm and writes transposed out.
#define STG_PITCH 144
#define G_BLOCKS  128

__global__ void __launch_bounds__(512, 1)
gemm_kernel(float* __restrict__ out) {
    __shared__ __align__(16) char stg[64 * STG_PITCH];   // 9216 B
    __shared__ float trs[64 * 65];                       // transpose buffer
    __shared__ int is_last;
    int t   = threadIdx.x;           // 512
    int lid = t & 31;
    int wid = t >> 5;                // 0..15
    int mt  = blockIdx.x >> 3;       // 0..15
    int ks  = blockIdx.x & 7;        // 0..7
    int d0  = mt * 64;
    int kb  = ks * 1024;
    int ms  = wid & 3;               // m-strip 0..3
    int kq  = wid >> 2;              // k-quarter 0..3
    int dw  = d0 + ms * 16;

    // B staging: thread copies one uint4 per chunk: row = t/8 (n), 16B chunk t%8.
    int brow = t >> 3, bch = t & 7;
    const uint4* bsrc =
        reinterpret_cast<const uint4*>(g_simN + (size_t)brow * S_MAX + kb) + bch;
    char* sts_p = stg + brow * STG_PITCH + bch * 16;

    // A source: W rows dw+lid/4 (+8), k = kb + kq*16 + 2*(lid&3) (+8).
    const __half* wp0 = g_W + (size_t)(dw + (lid >> 2)) * S_MAX
                        + kb + kq * 16 + 2 * (lid & 3);

    // B ldsm lane base within staged chunk.
    int  rown = (lid & 7) + ((lid >> 4) << 3);
    uint32_t lb = smem_u32(stg) + (uint32_t)rown * STG_PITCH
                  + kq * 32 + (((lid >> 3) & 1) << 4);

    float c[8][4];
    #pragma unroll
    for (int j = 0; j < 8; j++) { c[j][0] = c[j][1] = c[j][2] = c[j][3] = 0.f; }

    uint4 bv = bsrc[0];
    uint32_t a0 = *reinterpret_cast<const uint32_t*>(wp0);
    uint32_t a1 = *reinterpret_cast<const uint32_t*>(wp0 + 8 * S_MAX);
    uint32_t a2 = *reinterpret_cast<const uint32_t*>(wp0 + 8);
    uint32_t a3 = *reinterpret_cast<const uint32_t*>(wp0 + 8 * S_MAX + 8);

    #pragma unroll 1
    for (int ch = 0; ch < 16; ch++) {
        __syncthreads();                       // prior chunk fully consumed
        *reinterpret_cast<uint4*>(sts_p) = bv;
        uint32_t af[4] = {a0, a1, a2, a3};
        if (ch < 15) {                         // prefetch next chunk
            bv = bsrc[(ch + 1) * 8];
            const __half* wp = wp0 + (ch + 1) * 64;
            a0 = *reinterpret_cast<const uint32_t*>(wp);
            a1 = *reinterpret_cast<const uint32_t*>(wp + 8 * S_MAX);
            a2 = *reinterpret_cast<const uint32_t*>(wp + 8);
            a3 = *reinterpret_cast<const uint32_t*>(wp + 8 * S_MAX + 8);
        }
        __syncthreads();                       // staged chunk visible
        #pragma unroll
        for (int jj = 0; jj < 4; jj++) {       // 8 n-tiles as 4 ldsm.x4
            uint32_t b[4];
            LDSM_X4(b, lb + jj * (16 * STG_PITCH));
            mma_f16(c[2 * jj],     af, b[0], b[1]);
            mma_f16(c[2 * jj + 1], af, b[2], b[3]);
        }
    }

    // RED partials into g_C[d][b].
    {
        int rbase = (dw + (lid >> 2)) * 64 + 2 * (lid & 3);
        #pragma unroll
        for (int j = 0; j < 8; j++) {
            int b0i = rbase + 8 * j;
            atomicAdd(&g_C[b0i],           c[j][0]);
            atomicAdd(&g_C[b0i + 1],       c[j][1]);
            atomicAdd(&g_C[b0i + 512],     c[j][2]);   // +8 rows * 64
            atomicAdd(&g_C[b0i + 513],     c[j][3]);
        }
    }

    // Decoupled completion: last block scales + transposes to out[b][d].
    __threadfence();
    if (t == 0) is_last = (atomicAdd(&g_tick2, 1) == G_BLOCKS - 1) ? 1 : 0;
    __syncthreads();
    if (!is_last) return;

    for (int dc = 0; dc < 16; dc++) {          // 16 chunks of 64 diseases
        __syncthreads();
        for (int i = t; i < 4096; i += 512) trs[(i >> 6) * 65 + (i & 63)] = g_C[dc * 4096 + i];
        __syncthreads();
        for (int i = t; i < 4096; i += 512) {
            int b  = i >> 6;
            int dl = i & 63;
            out[(size_t)b * D_MAX + dc * 64 + dl] =
                ETA * g_gnorm[b] * trs[dl * 65 + b];
        }
    }
    if (t == 0) g_tick2 = 0;                   // reset for graph replay
}

// ---------------- launch: single stream, 3 kernels ---------------------------
extern "C" void kernel_launch(void* const* d_in, const int* in_sizes, int n_in,
                              void* d_out, int out_size) {
    const float* H  = (const float*)d_in[0];   // [B,F]
    const float* G  = (const float*)d_in[1];   // [B,F]
    const float* SF = (const float*)d_in[2];   // [S,F]
    const float* ew = (const float*)d_in[3];   // [E]
    const int*   ed = (const int*)d_in[4];     // [E]
    const int*   es = (const int*)d_in[5];     // [E]
    float* out = (float*)d_out;

    int E  = in_sizes[3];                      // 500000
    int CH = (E + NSCAT - 1) / NSCAT;          // edges per scatter block

    static int smem_set = 0;
    if (!smem_set) {
        cudaFuncSetAttribute(fused_kernel,
                             cudaFuncAttributeMaxDynamicSharedMemorySize,
                             FS_SMEM);
        smem_set = 1;
    }

    combo_kernel<<<146, 512>>>(H, G);
    fused_kernel<<<NSIM + NSCAT, 512, FS_SMEM>>>(SF, ew, ed, es, E, CH);
    gemm_kernel<<<G_BLOCKS, 512>>>(out);
}